// round 3
// baseline (speedup 1.0000x reference)
#include <cuda_runtime.h>
#include <cstdint>

#define N_NODES 100000
#define N_EDGES 1600000
#define IN_CH   512
#define HID     128
#define OUT_CH  64
#define SCAN_BLK ((N_NODES + 255) / 256)   // 391

// ---------------- scratch (device globals; no allocation allowed) ----------
__device__ float g_bufA[(size_t)N_NODES * HID];
__device__ float g_bufB[(size_t)N_NODES * HID];
__device__ float g_dinv[N_NODES];
__device__ int   g_count[N_NODES];
__device__ int   g_fill[N_NODES];
__device__ int   g_rowptr[N_NODES + 1];
__device__ int   g_col[N_EDGES];
__device__ float g_val[N_EDGES];
__device__ int   g_part[SCAN_BLK];
__device__ int   g_pscan[SCAN_BLK];
__device__ int   g_is64;

// ---------------- helpers --------------------------------------------------
__device__ __forceinline__ float gelu_exact(float v) {
    return 0.5f * v * (1.0f + erff(v * 0.7071067811865476f));
}

__device__ __forceinline__ int clampN(int v) {
    return min(max(v, 0), N_NODES - 1);
}

// Read edge endpoint k (element index) regardless of int64/int32 storage.
__device__ __forceinline__ int edge_at(const void* ei, int k) {
    if (g_is64) return (int)((const long long*)ei)[k];
    return ((const int*)ei)[k];
}

// ---------------- dtype probe ----------------------------------------------
// int64 values < 2^32 (node ids) have zero high words at odd int32 indices.
__global__ void dtype_probe_kernel(const int* __restrict__ a) {
    if (blockIdx.x == 0 && threadIdx.x == 0) {
        int all0 = 1;
        for (int i = 1; i < 64; i += 2) all0 &= (a[i] == 0);
        g_is64 = all0;
    }
}

// ---------------- SGEMM: C[M,BN] = A[M,K] @ B[K,BN] + bias ----------------
// BM=128, BK=8, TM=8, TN=BN/16, blockDim (16,16)
template <int BN>
__global__ void sgemm_bias_kernel(const float* __restrict__ A,
                                  const float* __restrict__ Bm,
                                  const float* __restrict__ bias,
                                  float* __restrict__ C,
                                  int M, int K) {
    constexpr int BM = 128, BK = 8, TM = 8, TN = BN / 16;
    __shared__ float As[BK][BM];
    __shared__ float Bs[BK][BN];

    const int tx = threadIdx.x, ty = threadIdx.y;
    const int tid = ty * 16 + tx;
    const int rowBase = blockIdx.x * BM;

    float acc[TM][TN];
#pragma unroll
    for (int i = 0; i < TM; i++)
#pragma unroll
        for (int j = 0; j < TN; j++) acc[i][j] = 0.0f;

    const int aRow = tid >> 1;
    const int aK   = (tid & 1) * 4;
    constexpr int numB4 = BK * BN / 4;
    const int bRow = tid / (BN / 4);
    const int bCol = (tid % (BN / 4)) * 4;

    for (int k0 = 0; k0 < K; k0 += BK) {
        int gRow = rowBase + aRow;
        float4 av = make_float4(0.f, 0.f, 0.f, 0.f);
        if (gRow < M)
            av = *(const float4*)(A + (size_t)gRow * K + k0 + aK);
        As[aK + 0][aRow] = av.x;
        As[aK + 1][aRow] = av.y;
        As[aK + 2][aRow] = av.z;
        As[aK + 3][aRow] = av.w;
        if (tid < numB4) {
            float4 bv = *(const float4*)(Bm + (size_t)(k0 + bRow) * BN + bCol);
            *(float4*)&Bs[bRow][bCol] = bv;
        }
        __syncthreads();
#pragma unroll
        for (int k = 0; k < BK; k++) {
            float a[TM], b[TN];
#pragma unroll
            for (int i = 0; i < TM; i++) a[i] = As[k][ty * TM + i];
#pragma unroll
            for (int j = 0; j < TN; j++) b[j] = Bs[k][tx * TN + j];
#pragma unroll
            for (int i = 0; i < TM; i++)
#pragma unroll
                for (int j = 0; j < TN; j++) acc[i][j] += a[i] * b[j];
        }
        __syncthreads();
    }

#pragma unroll
    for (int i = 0; i < TM; i++) {
        int r = rowBase + ty * TM + i;
        if (r < M) {
#pragma unroll
            for (int j = 0; j < TN; j++) {
                int c = tx * TN + j;
                C[(size_t)r * BN + c] = acc[i][j] + bias[c];
            }
        }
    }
}

// ---------------- fused exact-GELU + LayerNorm (warp per row, HID=128) -----
__global__ void gelu_ln_kernel(float* __restrict__ h,
                               const float* __restrict__ gamma,
                               const float* __restrict__ beta) {
    int gw = (blockIdx.x * blockDim.x + threadIdx.x) >> 5;
    int lane = threadIdx.x & 31;
    if (gw >= N_NODES) return;
    float4 v = ((const float4*)(h + (size_t)gw * HID))[lane];
    v.x = gelu_exact(v.x);
    v.y = gelu_exact(v.y);
    v.z = gelu_exact(v.z);
    v.w = gelu_exact(v.w);
    float s  = v.x + v.y + v.z + v.w;
    float sq = v.x * v.x + v.y * v.y + v.z * v.z + v.w * v.w;
#pragma unroll
    for (int off = 16; off > 0; off >>= 1) {
        s  += __shfl_xor_sync(0xffffffffu, s, off);
        sq += __shfl_xor_sync(0xffffffffu, sq, off);
    }
    float mu   = s * (1.0f / HID);
    float var  = sq * (1.0f / HID) - mu * mu;
    float rstd = rsqrtf(var + 1e-5f);
    float4 g = ((const float4*)gamma)[lane];
    float4 b = ((const float4*)beta)[lane];
    float4 o;
    o.x = (v.x - mu) * rstd * g.x + b.x;
    o.y = (v.y - mu) * rstd * g.y + b.y;
    o.z = (v.z - mu) * rstd * g.z + b.z;
    o.w = (v.w - mu) * rstd * g.w + b.w;
    ((float4*)(h + (size_t)gw * HID))[lane] = o;
}

// ---------------- CSR build ------------------------------------------------
__global__ void zero_counts_kernel() {
    int i = blockIdx.x * blockDim.x + threadIdx.x;
    if (i < N_NODES) { g_count[i] = 0; g_fill[i] = 0; }
}

__global__ void count_kernel(const void* __restrict__ ei) {
    int e = blockIdx.x * blockDim.x + threadIdx.x;
    if (e >= N_EDGES) return;
    int d = clampN(edge_at(ei, N_EDGES + e));
    atomicAdd(&g_count[d], 1);
}

__global__ void dinv_kernel() {
    int i = blockIdx.x * blockDim.x + threadIdx.x;
    if (i < N_NODES) g_dinv[i] = rsqrtf((float)(g_count[i] + 1));  // +1 self-loop
}

// Scan step 1: per-256-tile sums.
__global__ void part_sum_kernel() {
    __shared__ int sdata[256];
    int tid = threadIdx.x;
    int idx = blockIdx.x * 256 + tid;
    sdata[tid] = (idx < N_NODES) ? g_count[idx] : 0;
    __syncthreads();
    for (int s = 128; s > 0; s >>= 1) {
        if (tid < s) sdata[tid] += sdata[tid + s];
        __syncthreads();
    }
    if (tid == 0) g_part[blockIdx.x] = sdata[0];
}

// Scan step 2: single-thread exclusive scan of tile sums (391 entries).
__global__ void pscan_kernel() {
    if (blockIdx.x == 0 && threadIdx.x == 0) {
        int s = 0;
        for (int i = 0; i < SCAN_BLK; i++) {
            int t = g_part[i];
            g_pscan[i] = s;
            s += t;
        }
    }
}

// Scan step 3: per-tile exclusive scan + tile offset -> g_rowptr.
__global__ void rowptr_scan_kernel() {
    __shared__ int wsums[8];
    int tid = threadIdx.x;
    int lane = tid & 31;
    int wid = tid >> 5;
    int idx = blockIdx.x * 256 + tid;
    int v = (idx < N_NODES) ? g_count[idx] : 0;
    int incl = v;
#pragma unroll
    for (int off = 1; off < 32; off <<= 1) {
        int n = __shfl_up_sync(0xffffffffu, incl, off);
        if (lane >= off) incl += n;
    }
    if (lane == 31) wsums[wid] = incl;
    __syncthreads();
    if (tid == 0) {
        int s = 0;
#pragma unroll
        for (int i = 0; i < 8; i++) { int t = wsums[i]; wsums[i] = s; s += t; }
    }
    __syncthreads();
    int excl = incl - v + wsums[wid] + g_pscan[blockIdx.x];
    if (idx <= N_NODES) g_rowptr[idx] = excl;
}

__global__ void fill_kernel(const void* __restrict__ ei) {
    int e = blockIdx.x * blockDim.x + threadIdx.x;
    if (e >= N_EDGES) return;
    int s = clampN(edge_at(ei, e));
    int d = clampN(edge_at(ei, N_EDGES + e));
    int pos = g_rowptr[d] + atomicAdd(&g_fill[d], 1);
    pos = min(max(pos, 0), N_EDGES - 1);
    g_col[pos] = s;
    g_val[pos] = g_dinv[s] * g_dinv[d];
}

// ---------------- pull-mode SpMM hop (warp per dst row) ---------------------
// Y[d] = dinv[d]^2 * X[d] + sum_{e: dst=d} val[e] * X[col[e]]
__global__ void spmm_hop_kernel(const float* __restrict__ X,
                                float* __restrict__ Y) {
    int row = (blockIdx.x * blockDim.x + threadIdx.x) >> 5;
    int lane = threadIdx.x & 31;
    if (row >= N_NODES) return;
    int start = g_rowptr[row];
    int end   = g_rowptr[row + 1];
    start = min(max(start, 0), N_EDGES);
    end   = min(max(end, start), N_EDGES);
    float di = g_dinv[row];
    float w0 = di * di;
    float4 v = ((const float4*)(X + (size_t)row * HID))[lane];
    float4 acc;
    acc.x = w0 * v.x; acc.y = w0 * v.y; acc.z = w0 * v.z; acc.w = w0 * v.w;

    for (int j = start; j < end; j += 32) {
        int idx = j + lane;
        int c = 0;
        float wv = 0.0f;
        if (idx < end) { c = clampN(g_col[idx]); wv = g_val[idx]; }
        int cnt = min(32, end - j);
        for (int t = 0; t < cnt; t++) {
            int cc   = __shfl_sync(0xffffffffu, c, t);
            float ww = __shfl_sync(0xffffffffu, wv, t);
            float4 xv = ((const float4*)(X + (size_t)cc * HID))[lane];
            acc.x += ww * xv.x;
            acc.y += ww * xv.y;
            acc.z += ww * xv.z;
            acc.w += ww * xv.w;
        }
    }
    ((float4*)(Y + (size_t)row * HID))[lane] = acc;
}

// ---------------- launch ----------------------------------------------------
extern "C" void kernel_launch(void* const* d_in, const int* in_sizes, int n_in,
                              void* d_out, int out_size) {
    const float* x   = (const float*)d_in[0];
    const void*  ei  = d_in[1];
    const float* W1  = (const float*)d_in[2];
    const float* b1  = (const float*)d_in[3];
    const float* g1  = (const float*)d_in[4];
    const float* be1 = (const float*)d_in[5];
    const float* Wc  = (const float*)d_in[6];
    const float* bc  = (const float*)d_in[7];
    const float* g2  = (const float*)d_in[8];
    const float* be2 = (const float*)d_in[9];
    const float* W2  = (const float*)d_in[10];
    const float* b2  = (const float*)d_in[11];
    float* out = (float*)d_out;

    float *bufA, *bufB;
    cudaGetSymbolAddress((void**)&bufA, g_bufA);
    cudaGetSymbolAddress((void**)&bufB, g_bufB);

    const dim3 gemmBlk(16, 16);
    const int gemmGrid = (N_NODES + 127) / 128;
    const int rowWarpGrid = (N_NODES * 32 + 255) / 256;  // warp per row
    const int nodeGrid = (N_NODES + 255) / 256;          // == SCAN_BLK
    const int edgeGrid = (N_EDGES + 255) / 256;
    const int rpGrid = (N_NODES + 1 + 255) / 256;

    // Stage 1: h = LN(GELU(x @ W1 + b1))
    sgemm_bias_kernel<HID><<<gemmGrid, gemmBlk>>>(x, W1, b1, bufA, N_NODES, IN_CH);
    gelu_ln_kernel<<<rowWarpGrid, 256>>>(bufA, g1, be1);

    // CSR build (by dst) + normalization
    dtype_probe_kernel<<<1, 32>>>((const int*)ei);
    zero_counts_kernel<<<nodeGrid, 256>>>();
    count_kernel<<<edgeGrid, 256>>>(ei);
    dinv_kernel<<<nodeGrid, 256>>>();
    part_sum_kernel<<<SCAN_BLK, 256>>>();
    pscan_kernel<<<1, 32>>>();
    rowptr_scan_kernel<<<rpGrid, 256>>>();
    fill_kernel<<<edgeGrid, 256>>>(ei);

    // Hop 1: A -> B ; Hop 2: B -> A  (pull mode, no atomics)
    spmm_hop_kernel<<<rowWarpGrid, 256>>>(bufA, bufB);
    spmm_hop_kernel<<<rowWarpGrid, 256>>>(bufB, bufA);

    // Stage 3: h = LN(GELU(h @ Wc + bc)); out = h @ W2 + b2
    sgemm_bias_kernel<HID><<<gemmGrid, gemmBlk>>>(bufA, Wc, bc, bufB, N_NODES, HID);
    gelu_ln_kernel<<<rowWarpGrid, 256>>>(bufB, g2, be2);
    sgemm_bias_kernel<OUT_CH><<<gemmGrid, gemmBlk>>>(bufB, W2, b2, out, N_NODES, HID);
}

// round 4
// speedup vs baseline: 1.2284x; 1.2284x over previous
#include <cuda_runtime.h>
#include <mma.h>
#include <cstdint>

using namespace nvcuda;

#define N_NODES 100000
#define N_EDGES 1600000
#define IN_CH   512
#define HID     128
#define OUT_CH  64
#define SCAN_BLK ((N_NODES + 255) / 256)   // 391
#define M_TILES  ((N_NODES + 127) / 128)   // 782
#define M_PAD    (M_TILES * 128)           // 100096

// ---------------- scratch (device globals; no allocation allowed) ----------
__device__ float g_bufA[(size_t)M_PAD * HID];
__device__ float g_bufB[(size_t)M_PAD * HID];
__device__ float g_dinv[N_NODES];
__device__ int   g_count[N_NODES];
__device__ int   g_fill[N_NODES];
__device__ int   g_rowptr[N_NODES + 1];
__device__ int   g_col[N_EDGES];
__device__ float g_val[N_EDGES];
__device__ int   g_part[SCAN_BLK];
__device__ int   g_pscan[SCAN_BLK];
__device__ int   g_is64;

// ---------------- helpers --------------------------------------------------
__device__ __forceinline__ float gelu_exact(float v) {
    return 0.5f * v * (1.0f + erff(v * 0.7071067811865476f));
}

__device__ __forceinline__ int clampN(int v) {
    return min(max(v, 0), N_NODES - 1);
}

__device__ __forceinline__ int edge_at(const void* ei, int k) {
    if (g_is64) return (int)((const long long*)ei)[k];
    return ((const int*)ei)[k];
}

__global__ void dtype_probe_kernel(const int* __restrict__ a) {
    if (blockIdx.x == 0 && threadIdx.x == 0) {
        int all0 = 1;
        for (int i = 1; i < 64; i += 2) all0 &= (a[i] == 0);
        g_is64 = all0;
    }
}

// ---------------- tf32 WMMA GEMM: C[M_PAD, BN] = A[M,K] @ B[K,BN] ---------
// BM=128, BK=32, 8 warps. BN=128: warp tile 32x64 (grid 4x2).
//                         BN=64 : warp tile 32x32 (grid 4x2), staged epilogue
//                                 with row guard + bias (for writing d_out).
template <int BN, bool STAGED>
__global__ void __launch_bounds__(256, 1)
wmma_gemm_kernel(const float* __restrict__ A,
                 const float* __restrict__ Bm,
                 const float* __restrict__ bias,
                 float* __restrict__ C,
                 int M, int K) {
    constexpr int BM = 128, BK = 32;
    constexpr int LDA = BK + 4;        // 36
    constexpr int LDB = BN + 4;        // 132 / 68
    constexpr int WN = (BN == 128) ? 4 : 2;   // 16-col frags per warp

    struct SmemT {
        float As[BM][LDA];
        float Bs[BK][LDB];
    };
    constexpr size_t SMEM_BYTES =
        (STAGED && sizeof(SmemT) < (size_t)BM * BN * 4) ? (size_t)BM * BN * 4
                                                        : sizeof(SmemT);
    __shared__ __align__(16) char smem_raw[SMEM_BYTES];
    SmemT& sm = *reinterpret_cast<SmemT*>(smem_raw);

    const int tid  = threadIdx.x;
    const int wid  = tid >> 5;
    const int warpM = wid & 3;          // 0..3 -> 32-row slab
    const int warpN = wid >> 2;         // 0..1 -> WN*16-col slab
    const int rowBase = blockIdx.x * BM;

    wmma::fragment<wmma::accumulator, 16, 16, 8, float> acc[2][WN];
#pragma unroll
    for (int i = 0; i < 2; i++)
#pragma unroll
        for (int j = 0; j < WN; j++) wmma::fill_fragment(acc[i][j], 0.0f);

    for (int k0 = 0; k0 < K; k0 += BK) {
        // ---- load A tile: BM x BK (1024 float4, 4 per thread) ----
#pragma unroll
        for (int i = 0; i < 4; i++) {
            int lin = tid + i * 256;          // float4 index
            int r = lin >> 3;                 // 8 float4 per row
            int c = (lin & 7) * 4;
            float4 v = make_float4(0.f, 0.f, 0.f, 0.f);
            int gr = rowBase + r;
            if (gr < M) v = *(const float4*)(A + (size_t)gr * K + k0 + c);
            sm.As[r][c + 0] = v.x;
            sm.As[r][c + 1] = v.y;
            sm.As[r][c + 2] = v.z;
            sm.As[r][c + 3] = v.w;
        }
        // ---- load B tile: BK x BN ----
        constexpr int B4 = BK * BN / 4;       // 1024 or 512
#pragma unroll
        for (int i = 0; i < B4 / 256; i++) {
            int lin = tid + i * 256;
            int r = lin / (BN / 4);
            int c = (lin % (BN / 4)) * 4;
            float4 v = *(const float4*)(Bm + (size_t)(k0 + r) * BN + c);
            sm.Bs[r][c + 0] = v.x;
            sm.Bs[r][c + 1] = v.y;
            sm.Bs[r][c + 2] = v.z;
            sm.Bs[r][c + 3] = v.w;
        }
        __syncthreads();

#pragma unroll
        for (int kk = 0; kk < BK; kk += 8) {
            wmma::fragment<wmma::matrix_a, 16, 16, 8, wmma::precision::tf32,
                           wmma::row_major> af[2];
            wmma::fragment<wmma::matrix_b, 16, 16, 8, wmma::precision::tf32,
                           wmma::row_major> bf[WN];
#pragma unroll
            for (int i = 0; i < 2; i++) {
                wmma::load_matrix_sync(af[i], &sm.As[warpM * 32 + i * 16][kk], LDA);
#pragma unroll
                for (int t = 0; t < af[i].num_elements; t++)
                    af[i].x[t] = wmma::__float_to_tf32(af[i].x[t]);
            }
#pragma unroll
            for (int j = 0; j < WN; j++) {
                wmma::load_matrix_sync(bf[j], &sm.Bs[kk][warpN * WN * 16 + j * 16], LDB);
#pragma unroll
                for (int t = 0; t < bf[j].num_elements; t++)
                    bf[j].x[t] = wmma::__float_to_tf32(bf[j].x[t]);
            }
#pragma unroll
            for (int i = 0; i < 2; i++)
#pragma unroll
                for (int j = 0; j < WN; j++)
                    wmma::mma_sync(acc[i][j], af[i], bf[j], acc[i][j]);
        }
        __syncthreads();
    }

    if (!STAGED) {
        // direct store into padded buffer (rows beyond M are scratch)
#pragma unroll
        for (int i = 0; i < 2; i++)
#pragma unroll
            for (int j = 0; j < WN; j++) {
                int r = rowBase + warpM * 32 + i * 16;
                int c = warpN * WN * 16 + j * 16;
                wmma::store_matrix_sync(C + (size_t)r * BN + c, acc[i][j], BN,
                                        wmma::mem_row_major);
            }
    } else {
        // stage through smem, guard rows, add bias
        float* Cs = reinterpret_cast<float*>(smem_raw);
#pragma unroll
        for (int i = 0; i < 2; i++)
#pragma unroll
            for (int j = 0; j < WN; j++) {
                int r = warpM * 32 + i * 16;
                int c = warpN * WN * 16 + j * 16;
                wmma::store_matrix_sync(Cs + (size_t)r * BN + c, acc[i][j], BN,
                                        wmma::mem_row_major);
            }
        __syncthreads();
        constexpr int C4 = BM * BN / 4;
#pragma unroll
        for (int i = 0; i < C4 / 256; i++) {
            int lin = tid + i * 256;
            int r = lin / (BN / 4);
            int c = (lin % (BN / 4)) * 4;
            int gr = rowBase + r;
            if (gr < M) {
                float4 v = *(float4*)(Cs + (size_t)r * BN + c);
                v.x += bias[c + 0];
                v.y += bias[c + 1];
                v.z += bias[c + 2];
                v.w += bias[c + 3];
                *(float4*)(C + (size_t)gr * BN + c) = v;
            }
        }
    }
}

// ---------------- fused bias + exact-GELU + LayerNorm (warp/row, HID=128) --
__global__ void gelu_ln_kernel(float* __restrict__ h,
                               const float* __restrict__ bias,
                               const float* __restrict__ gamma,
                               const float* __restrict__ beta) {
    int gw = (blockIdx.x * blockDim.x + threadIdx.x) >> 5;
    int lane = threadIdx.x & 31;
    if (gw >= N_NODES) return;
    float4 v = ((const float4*)(h + (size_t)gw * HID))[lane];
    float4 bb = ((const float4*)bias)[lane];
    v.x = gelu_exact(v.x + bb.x);
    v.y = gelu_exact(v.y + bb.y);
    v.z = gelu_exact(v.z + bb.z);
    v.w = gelu_exact(v.w + bb.w);
    float s  = v.x + v.y + v.z + v.w;
    float sq = v.x * v.x + v.y * v.y + v.z * v.z + v.w * v.w;
#pragma unroll
    for (int off = 16; off > 0; off >>= 1) {
        s  += __shfl_xor_sync(0xffffffffu, s, off);
        sq += __shfl_xor_sync(0xffffffffu, sq, off);
    }
    float mu   = s * (1.0f / HID);
    float var  = sq * (1.0f / HID) - mu * mu;
    float rstd = rsqrtf(var + 1e-5f);
    float4 g = ((const float4*)gamma)[lane];
    float4 b = ((const float4*)beta)[lane];
    float4 o;
    o.x = (v.x - mu) * rstd * g.x + b.x;
    o.y = (v.y - mu) * rstd * g.y + b.y;
    o.z = (v.z - mu) * rstd * g.z + b.z;
    o.w = (v.w - mu) * rstd * g.w + b.w;
    ((float4*)(h + (size_t)gw * HID))[lane] = o;
}

// ---------------- CSR build ------------------------------------------------
__global__ void zero_counts_kernel() {
    int i = blockIdx.x * blockDim.x + threadIdx.x;
    if (i < N_NODES) { g_count[i] = 0; g_fill[i] = 0; }
}

__global__ void count_kernel(const void* __restrict__ ei) {
    int e = blockIdx.x * blockDim.x + threadIdx.x;
    if (e >= N_EDGES) return;
    int d = clampN(edge_at(ei, N_EDGES + e));
    atomicAdd(&g_count[d], 1);
}

__global__ void dinv_kernel() {
    int i = blockIdx.x * blockDim.x + threadIdx.x;
    if (i < N_NODES) g_dinv[i] = rsqrtf((float)(g_count[i] + 1));  // +1 self-loop
}

__global__ void part_sum_kernel() {
    __shared__ int sdata[256];
    int tid = threadIdx.x;
    int idx = blockIdx.x * 256 + tid;
    sdata[tid] = (idx < N_NODES) ? g_count[idx] : 0;
    __syncthreads();
    for (int s = 128; s > 0; s >>= 1) {
        if (tid < s) sdata[tid] += sdata[tid + s];
        __syncthreads();
    }
    if (tid == 0) g_part[blockIdx.x] = sdata[0];
}

__global__ void pscan_kernel() {
    if (blockIdx.x == 0 && threadIdx.x == 0) {
        int s = 0;
        for (int i = 0; i < SCAN_BLK; i++) {
            int t = g_part[i];
            g_pscan[i] = s;
            s += t;
        }
    }
}

__global__ void rowptr_scan_kernel() {
    __shared__ int wsums[8];
    int tid = threadIdx.x;
    int lane = tid & 31;
    int wid = tid >> 5;
    int idx = blockIdx.x * 256 + tid;
    int v = (idx < N_NODES) ? g_count[idx] : 0;
    int incl = v;
#pragma unroll
    for (int off = 1; off < 32; off <<= 1) {
        int n = __shfl_up_sync(0xffffffffu, incl, off);
        if (lane >= off) incl += n;
    }
    if (lane == 31) wsums[wid] = incl;
    __syncthreads();
    if (tid == 0) {
        int s = 0;
#pragma unroll
        for (int i = 0; i < 8; i++) { int t = wsums[i]; wsums[i] = s; s += t; }
    }
    __syncthreads();
    int excl = incl - v + wsums[wid] + g_pscan[blockIdx.x];
    if (idx <= N_NODES) g_rowptr[idx] = excl;
}

__global__ void fill_kernel(const void* __restrict__ ei) {
    int e = blockIdx.x * blockDim.x + threadIdx.x;
    if (e >= N_EDGES) return;
    int s = clampN(edge_at(ei, e));
    int d = clampN(edge_at(ei, N_EDGES + e));
    int pos = g_rowptr[d] + atomicAdd(&g_fill[d], 1);
    pos = min(max(pos, 0), N_EDGES - 1);
    g_col[pos] = s;
    g_val[pos] = g_dinv[s] * g_dinv[d];
}

// ---------------- pull-mode SpMM hop (warp per dst row) ---------------------
__global__ void spmm_hop_kernel(const float* __restrict__ X,
                                float* __restrict__ Y) {
    int row = (blockIdx.x * blockDim.x + threadIdx.x) >> 5;
    int lane = threadIdx.x & 31;
    if (row >= N_NODES) return;
    int start = g_rowptr[row];
    int end   = g_rowptr[row + 1];
    start = min(max(start, 0), N_EDGES);
    end   = min(max(end, start), N_EDGES);
    float di = g_dinv[row];
    float w0 = di * di;
    float4 v = ((const float4*)(X + (size_t)row * HID))[lane];
    float4 acc;
    acc.x = w0 * v.x; acc.y = w0 * v.y; acc.z = w0 * v.z; acc.w = w0 * v.w;

    for (int j = start; j < end; j += 32) {
        int idx = j + lane;
        int c = 0;
        float wv = 0.0f;
        if (idx < end) { c = clampN(g_col[idx]); wv = g_val[idx]; }
        int cnt = min(32, end - j);
        for (int t = 0; t < cnt; t++) {
            int cc   = __shfl_sync(0xffffffffu, c, t);
            float ww = __shfl_sync(0xffffffffu, wv, t);
            float4 xv = ((const float4*)(X + (size_t)cc * HID))[lane];
            acc.x += ww * xv.x;
            acc.y += ww * xv.y;
            acc.z += ww * xv.z;
            acc.w += ww * xv.w;
        }
    }
    ((float4*)(Y + (size_t)row * HID))[lane] = acc;
}

// ---------------- launch ----------------------------------------------------
extern "C" void kernel_launch(void* const* d_in, const int* in_sizes, int n_in,
                              void* d_out, int out_size) {
    const float* x   = (const float*)d_in[0];
    const void*  ei  = d_in[1];
    const float* W1  = (const float*)d_in[2];
    const float* b1  = (const float*)d_in[3];
    const float* g1  = (const float*)d_in[4];
    const float* be1 = (const float*)d_in[5];
    const float* Wc  = (const float*)d_in[6];
    const float* bc  = (const float*)d_in[7];
    const float* g2  = (const float*)d_in[8];
    const float* be2 = (const float*)d_in[9];
    const float* W2  = (const float*)d_in[10];
    const float* b2  = (const float*)d_in[11];
    float* out = (float*)d_out;

    float *bufA, *bufB;
    cudaGetSymbolAddress((void**)&bufA, g_bufA);
    cudaGetSymbolAddress((void**)&bufB, g_bufB);

    const int gemmGrid = M_TILES;                        // 782
    const int rowWarpGrid = (N_NODES * 32 + 255) / 256;  // warp per row
    const int nodeGrid = (N_NODES + 255) / 256;
    const int edgeGrid = (N_EDGES + 255) / 256;
    const int rpGrid = (N_NODES + 1 + 255) / 256;

    // Stage 1: h = LN(GELU(x @ W1 + b1))
    wmma_gemm_kernel<HID, false><<<gemmGrid, 256>>>(x, W1, b1, bufA, N_NODES, IN_CH);
    gelu_ln_kernel<<<rowWarpGrid, 256>>>(bufA, b1, g1, be1);

    // CSR build (by dst) + normalization
    dtype_probe_kernel<<<1, 32>>>((const int*)ei);
    zero_counts_kernel<<<nodeGrid, 256>>>();
    count_kernel<<<edgeGrid, 256>>>(ei);
    dinv_kernel<<<nodeGrid, 256>>>();
    part_sum_kernel<<<SCAN_BLK, 256>>>();
    pscan_kernel<<<1, 32>>>();
    rowptr_scan_kernel<<<rpGrid, 256>>>();
    fill_kernel<<<edgeGrid, 256>>>(ei);

    // Hop 1: A -> B ; Hop 2: B -> A  (pull mode, no atomics)
    spmm_hop_kernel<<<rowWarpGrid, 256>>>(bufA, bufB);
    spmm_hop_kernel<<<rowWarpGrid, 256>>>(bufB, bufA);

    // Stage 3: h = LN(GELU(h @ Wc + bc)); out = h @ W2 + b2
    wmma_gemm_kernel<HID, false><<<gemmGrid, 256>>>(bufA, Wc, bc, bufB, N_NODES, HID);
    gelu_ln_kernel<<<rowWarpGrid, 256>>>(bufB, bc, g2, be2);
    wmma_gemm_kernel<OUT_CH, true><<<gemmGrid, 256>>>(bufB, W2, b2, out, N_NODES, HID);
}